// round 7
// baseline (speedup 1.0000x reference)
#include <cuda_runtime.h>
#include <cuda_bf16.h>
#include <math.h>
#include <stdint.h>

#define B_SZ  4
#define S_LEN 2048
#define D_DIM 1024
#define M_ROWS (B_SZ * S_LEN)   // 8192

typedef __nv_bfloat16 bf16;

// ---------------- scratch (allocation-free: __device__ globals) ----------------
__device__ bf16  g_Xhi[(size_t)M_ROWS * D_DIM];
__device__ bf16  g_Xlo[(size_t)M_ROWS * D_DIM];
__device__ bf16  g_Whi[(size_t)3 * D_DIM * D_DIM];   // [3072][1024] = wq|wk|wv rows
__device__ bf16  g_Wlo[(size_t)3 * D_DIM * D_DIM];
__device__ bf16  g_Qhi[(size_t)M_ROWS * D_DIM];
__device__ bf16  g_Qlo[(size_t)M_ROWS * D_DIM];
__device__ bf16  g_Khi[(size_t)M_ROWS * D_DIM];
__device__ bf16  g_Klo[(size_t)M_ROWS * D_DIM];
__device__ bf16  g_Vhi[(size_t)M_ROWS * D_DIM];      // row-major [b*S+s][d]
__device__ bf16  g_Vlo[(size_t)M_ROWS * D_DIM];
__device__ float g_S  [(size_t)B_SZ * S_LEN * S_LEN];
__device__ bf16  g_Phi[(size_t)B_SZ * S_LEN * S_LEN];
__device__ bf16  g_Plo[(size_t)B_SZ * S_LEN * S_LEN];

// ======================= helpers =======================
__device__ __forceinline__ uint32_t smem_u32(const void* p) {
    uint32_t a;
    asm("{ .reg .u64 t; cvta.to.shared.u64 t, %1; cvt.u32.u64 %0, t; }" : "=r"(a) : "l"(p));
    return a;
}
__device__ __forceinline__ void split2(float a, float b, uint32_t& h, uint32_t& l) {
    bf16 ah = __float2bfloat16(a), bh = __float2bfloat16(b);
    bf16 al = __float2bfloat16(a - __bfloat162float(ah));
    bf16 bl = __float2bfloat16(b - __bfloat162float(bh));
    h = (uint32_t)__bfloat16_as_ushort(ah) | ((uint32_t)__bfloat16_as_ushort(bh) << 16);
    l = (uint32_t)__bfloat16_as_ushort(al) | ((uint32_t)__bfloat16_as_ushort(bl) << 16);
}
__device__ __forceinline__ void ldsm4(uint32_t& r0, uint32_t& r1, uint32_t& r2, uint32_t& r3,
                                      uint32_t addr) {
    asm volatile("ldmatrix.sync.aligned.m8n8.x4.shared.b16 {%0,%1,%2,%3}, [%4];"
                 : "=r"(r0), "=r"(r1), "=r"(r2), "=r"(r3) : "r"(addr));
}
__device__ __forceinline__ void ldsm4t(uint32_t& r0, uint32_t& r1, uint32_t& r2, uint32_t& r3,
                                       uint32_t addr) {
    asm volatile("ldmatrix.sync.aligned.m8n8.x4.trans.shared.b16 {%0,%1,%2,%3}, [%4];"
                 : "=r"(r0), "=r"(r1), "=r"(r2), "=r"(r3) : "r"(addr));
}
__device__ __forceinline__ void mma16816(float& d0, float& d1, float& d2, float& d3,
                                         uint32_t a0, uint32_t a1, uint32_t a2, uint32_t a3,
                                         uint32_t b0, uint32_t b1) {
    asm volatile(
        "mma.sync.aligned.m16n8k16.row.col.f32.bf16.bf16.f32 "
        "{%0,%1,%2,%3},{%4,%5,%6,%7},{%8,%9},{%0,%1,%2,%3};"
        : "+f"(d0), "+f"(d1), "+f"(d2), "+f"(d3)
        : "r"(a0), "r"(a1), "r"(a2), "r"(a3), "r"(b0), "r"(b1));
}
__device__ __forceinline__ void cp16(uint32_t dst, const void* src) {
    asm volatile("cp.async.cg.shared.global [%0], [%1], 16;"
                 :: "r"(dst), "l"(__cvta_generic_to_global(src)) : "memory");
}
#define CP_COMMIT() asm volatile("cp.async.commit_group;" ::: "memory")
#define CP_WAIT1()  asm volatile("cp.async.wait_group 1;" ::: "memory")

// A / NT-B plane tiles: [rows][32 bf16] = 64B rows; chunk c(0..3) ^= (row>>1)&3
__device__ __forceinline__ uint32_t swp(int row, int chunk) {
    return (uint32_t)(row * 64 + ((chunk ^ ((row >> 1) & 3)) << 4));
}
// NN-B plane tile: [32 k-rows][256 n-cols] = 512B rows; chunk c(0..31) ^= k&7 (low 3 bits)
__device__ __forceinline__ uint32_t swb2(int k, int chunk) {
    return (uint32_t)(k * 512 + ((chunk ^ (k & 7)) << 4));
}

// CTA tile 128(M) x 256(N), BK=32, 8 warps (2x4), warp tile 64x64, 1 CTA/SM
#define TILE_A  8192                          // 128*32*2 per plane
#define TILE_BB 16384                         // 256*32*2 per plane
#define STAGE_BYTES (2 * TILE_A + 2 * TILE_BB)   // 49152
#define SMEM_GEMM_BYTES (3 * STAGE_BYTES)        // 147456

// ======================= shared mainloop =======================
// BMODE 0: B = [N,K] row-major (NT).  BMODE 1: B = [K,N] row-major (NN, ldmatrix.trans)
template<int BMODE>
__device__ __forceinline__ void issue_stage(
    uint32_t base, const bf16* Agh, const bf16* Agl,
    const bf16* Bgh, const bf16* Bgl, int K, int ldB, int tid, int c)
{
    const bf16* Ah = Agh + (long long)c * 32;
    const bf16* Al = Agl + (long long)c * 32;
    #pragma unroll
    for (int p = 0; p < 2; p++) {
        int cidx = tid + p * 256;
        int row = cidx >> 2, ch = cidx & 3;
        cp16(base + swp(row, ch),          Ah + (long long)row * K + ch * 8);
        cp16(base + TILE_A + swp(row, ch), Al + (long long)row * K + ch * 8);
    }
    if (BMODE == 0) {
        const bf16* Bh = Bgh + (long long)c * 32;
        const bf16* Bl = Bgl + (long long)c * 32;
        #pragma unroll
        for (int p = 0; p < 4; p++) {
            int cidx = tid + p * 256;
            int row = cidx >> 2, ch = cidx & 3;
            cp16(base + 2 * TILE_A + swp(row, ch),           Bh + (long long)row * K + ch * 8);
            cp16(base + 2 * TILE_A + TILE_BB + swp(row, ch), Bl + (long long)row * K + ch * 8);
        }
    } else {
        const bf16* Bh = Bgh + (long long)c * 32 * ldB;
        const bf16* Bl = Bgl + (long long)c * 32 * ldB;
        #pragma unroll
        for (int p = 0; p < 4; p++) {
            int cidx = tid + p * 256;
            int k = cidx >> 5, ch = cidx & 31;
            cp16(base + 2 * TILE_A + swb2(k, ch),           Bh + (long long)k * ldB + ch * 8);
            cp16(base + 2 * TILE_A + TILE_BB + swb2(k, ch), Bl + (long long)k * ldB + ch * 8);
        }
    }
    CP_COMMIT();
}

template<int BMODE>
__device__ __forceinline__ void gemm_mainloop(
    const bf16* Agh, const bf16* Agl, const bf16* Bgh, const bf16* Bgl,
    int K, int ldB, uint32_t sbase, int tid, float acc[4][8][4])
{
    const int wid = tid >> 5, lane = tid & 31;
    const int warpM = (wid >> 2) * 64, warpN = (wid & 3) * 64;
    const int NC = K >> 5;

    issue_stage<BMODE>(sbase,               Agh, Agl, Bgh, Bgl, K, ldB, tid, 0);
    issue_stage<BMODE>(sbase + STAGE_BYTES, Agh, Agl, Bgh, Bgl, K, ldB, tid, 1);

    // lane mappings
    const int laA = lane & 15, lcA = lane >> 4;          // A / NT-B
    const int laB = (lane & 7) + ((lane & 16) >> 1);
    const int lcB = (lane >> 3) & 1;
    const int lrT = lane & 7, gT = lane >> 3;            // NN-B trans

    for (int c = 0; c < NC; c++) {
        CP_WAIT1();
        __syncthreads();
        // safe: stage (c+2)%3 was consumed at iter c-1; all warps have passed this sync
        if (c + 2 < NC) {
            issue_stage<BMODE>(sbase + ((c + 2) % 3) * STAGE_BYTES,
                               Agh, Agl, Bgh, Bgl, K, ldB, tid, c + 2);
        } else {
            CP_COMMIT();
        }

        const uint32_t sAh = sbase + (c % 3) * STAGE_BYTES;
        const uint32_t sAl = sAh + TILE_A;
        const uint32_t sBh = sAh + 2 * TILE_A;
        const uint32_t sBl = sBh + TILE_BB;

        #pragma unroll
        for (int kk = 0; kk < 2; kk++) {
            uint32_t bhi[8][2], blo[8][2];
            if (BMODE == 0) {
                #pragma unroll
                for (int g = 0; g < 4; g++) {
                    int rB = warpN + g * 16 + laB;
                    uint32_t off = swp(rB, 2 * kk + lcB);
                    ldsm4(bhi[2*g][0], bhi[2*g][1], bhi[2*g+1][0], bhi[2*g+1][1], sBh + off);
                    ldsm4(blo[2*g][0], blo[2*g][1], blo[2*g+1][0], blo[2*g+1][1], sBl + off);
                }
            } else {
                int k = kk * 16 + (gT & 1) * 8 + lrT;
                int cb = (warpN >> 3) + (gT >> 1);
                #pragma unroll
                for (int j = 0; j < 4; j++) {
                    uint32_t off = swb2(k, cb + 2 * j);
                    ldsm4t(bhi[2*j][0], bhi[2*j][1], bhi[2*j+1][0], bhi[2*j+1][1], sBh + off);
                    ldsm4t(blo[2*j][0], blo[2*j][1], blo[2*j+1][0], blo[2*j+1][1], sBl + off);
                }
            }
            #pragma unroll
            for (int mt = 0; mt < 4; mt++) {
                int rA = warpM + mt * 16 + laA;
                uint32_t off = swp(rA, 2 * kk + lcA);
                uint32_t ah0, ah1, ah2, ah3, al0, al1, al2, al3;
                ldsm4(ah0, ah1, ah2, ah3, sAh + off);
                ldsm4(al0, al1, al2, al3, sAl + off);
                #pragma unroll
                for (int nt = 0; nt < 8; nt++)
                    mma16816(acc[mt][nt][0], acc[mt][nt][1], acc[mt][nt][2], acc[mt][nt][3],
                             ah0, ah1, ah2, ah3, bhi[nt][0], bhi[nt][1]);
                #pragma unroll
                for (int nt = 0; nt < 8; nt++)
                    mma16816(acc[mt][nt][0], acc[mt][nt][1], acc[mt][nt][2], acc[mt][nt][3],
                             ah0, ah1, ah2, ah3, blo[nt][0], blo[nt][1]);
                #pragma unroll
                for (int nt = 0; nt < 8; nt++)
                    mma16816(acc[mt][nt][0], acc[mt][nt][1], acc[mt][nt][2], acc[mt][nt][3],
                             al0, al1, al2, al3, bhi[nt][0], bhi[nt][1]);
            }
        }
    }
    __syncthreads();
}

// ======================= plain GEMM kernel (scores / PV) =======================
template<int BMODE>
__global__ void __launch_bounds__(256, 1) gemm_plain(
    const bf16* __restrict__ Ahi, const bf16* __restrict__ Alo,
    const bf16* __restrict__ Bhi, const bf16* __restrict__ Blo,
    float* __restrict__ C, int N, int K,
    long long sA, long long sB, long long sC, float alpha)
{
    extern __shared__ uint32_t sm[];
    const uint32_t sbase = smem_u32(sm);
    const int tid = threadIdx.x, wid = tid >> 5, lane = tid & 31;
    const int bm = blockIdx.y * 128, bn = blockIdx.x * 256;

    const bf16* Agh = Ahi + blockIdx.z * sA + (long long)bm * K;
    const bf16* Agl = Alo + blockIdx.z * sA + (long long)bm * K;
    const bf16 *Bgh, *Bgl;
    if (BMODE == 0) {
        Bgh = Bhi + blockIdx.z * sB + (long long)bn * K;
        Bgl = Blo + blockIdx.z * sB + (long long)bn * K;
    } else {
        Bgh = Bhi + blockIdx.z * sB + bn;
        Bgl = Blo + blockIdx.z * sB + bn;
    }

    float acc[4][8][4];
    #pragma unroll
    for (int m = 0; m < 4; m++)
        #pragma unroll
        for (int n = 0; n < 8; n++)
            #pragma unroll
            for (int e = 0; e < 4; e++) acc[m][n][e] = 0.0f;

    gemm_mainloop<BMODE>(Agh, Agl, Bgh, Bgl, K, (BMODE ? N : K), sbase, tid, acc);

    C += blockIdx.z * sC;
    const int warpM = (wid >> 2) * 64, warpN = (wid & 3) * 64;
    const int r = lane >> 2, q = lane & 3;
    #pragma unroll
    for (int mt = 0; mt < 4; mt++) {
        #pragma unroll
        for (int nt = 0; nt < 8; nt++) {
            int row = bm + warpM + mt * 16 + r;
            int col = bn + warpN + nt * 8 + q * 2;
            float2 o0 = make_float2(acc[mt][nt][0] * alpha, acc[mt][nt][1] * alpha);
            float2 o1 = make_float2(acc[mt][nt][2] * alpha, acc[mt][nt][3] * alpha);
            *(float2*)(C + (long long)row * N + col)       = o0;
            *(float2*)(C + (long long)(row + 8) * N + col) = o1;
        }
    }
}

// ======================= fused projection GEMM: QKV + bias + RoPE + split =======================
__global__ void __launch_bounds__(256, 1) gemm_proj(
    const bf16* __restrict__ Ahi, const bf16* __restrict__ Alo,
    const bf16* __restrict__ Bhi, const bf16* __restrict__ Blo,
    const float* __restrict__ bq, const float* __restrict__ bk, const float* __restrict__ bv,
    bf16* __restrict__ Qh, bf16* __restrict__ Ql,
    bf16* __restrict__ Kh, bf16* __restrict__ Kl,
    bf16* __restrict__ Vh, bf16* __restrict__ Vl)
{
    extern __shared__ uint32_t sm[];
    const uint32_t sbase = smem_u32(sm);
    const int tid = threadIdx.x, wid = tid >> 5, lane = tid & 31;
    const int bm = blockIdx.y * 128, bn = blockIdx.x * 256;
    const int K = D_DIM;

    const bf16* Agh = Ahi + (long long)bm * K;
    const bf16* Agl = Alo + (long long)bm * K;
    const bf16* Bgh = Bhi + (long long)bn * K;
    const bf16* Bgl = Blo + (long long)bn * K;

    float acc[4][8][4];
    #pragma unroll
    for (int m = 0; m < 4; m++)
        #pragma unroll
        for (int n = 0; n < 8; n++)
            #pragma unroll
            for (int e = 0; e < 4; e++) acc[m][n][e] = 0.0f;

    gemm_mainloop<0>(Agh, Agl, Bgh, Bgl, K, K, sbase, tid, acc);

    const int warpM = (wid >> 2) * 64, warpN = (wid & 3) * 64;
    const int r = lane >> 2, q = lane & 3;
    const int sel = bn >> 10;                   // uniform per CTA (bn multiple of 256)
    const float* bias = (sel == 0) ? bq : (sel == 1) ? bk : bv;
    uint32_t* Oh = (uint32_t*)((sel == 0) ? Qh : (sel == 1) ? Kh : Vh);
    uint32_t* Ol = (uint32_t*)((sel == 0) ? Ql : (sel == 1) ? Kl : Vl);

    #pragma unroll
    for (int nt = 0; nt < 8; nt++) {
        int col = bn + warpN + nt * 8 + q * 2;   // even
        int cl  = col & 1023;
        float b0 = bias[cl], b1 = bias[cl + 1];
        float invf = (sel < 2) ? powf(10000.0f, -(float)cl * (1.0f / (float)D_DIM)) : 0.0f;
        #pragma unroll
        for (int mt = 0; mt < 4; mt++) {
            #pragma unroll
            for (int rr = 0; rr < 2; rr++) {
                int row = bm + warpM + mt * 16 + r + rr * 8;
                float v0 = acc[mt][nt][rr * 2 + 0] + b0;
                float v1 = acc[mt][nt][rr * 2 + 1] + b1;
                if (sel < 2) {
                    int s = row & (S_LEN - 1);
                    float sn, cs;
                    sincosf((float)s * invf, &sn, &cs);
                    float t0 = v0 * cs - v1 * sn;
                    float t1 = v0 * sn + v1 * cs;
                    v0 = t0; v1 = t1;
                }
                uint32_t h, l;
                split2(v0, v1, h, l);
                long long off = (long long)row * (D_DIM / 2) + (cl >> 1);
                Oh[off] = h;
                Ol[off] = l;
            }
        }
    }
}

// ---------------- fp32 -> hi/lo plane conversion ----------------
__global__ void __launch_bounds__(256) split_kernel(const float* __restrict__ in,
                                                    bf16* __restrict__ hi,
                                                    bf16* __restrict__ lo, int n8)
{
    int i = blockIdx.x * 256 + threadIdx.x;
    if (i >= n8) return;
    const float4* in4 = (const float4*)in;
    float4 v0 = in4[2 * i], v1 = in4[2 * i + 1];
    uint4 h, l;
    split2(v0.x, v0.y, h.x, l.x);
    split2(v0.z, v0.w, h.y, l.y);
    split2(v1.x, v1.y, h.z, l.z);
    split2(v1.z, v1.w, h.w, l.w);
    ((uint4*)hi)[i] = h;
    ((uint4*)lo)[i] = l;
}

// ---------------- row softmax over S_LEN, fp32 in -> hi/lo planes out ----------------
__global__ void __launch_bounds__(256) softmax_split_kernel(
    const float* __restrict__ P, bf16* __restrict__ Phi, bf16* __restrict__ Plo)
{
    const float* row = P + (long long)blockIdx.x * S_LEN;
    bf16* rh = Phi + (long long)blockIdx.x * S_LEN;
    bf16* rl = Plo + (long long)blockIdx.x * S_LEN;
    const int tid = threadIdx.x;
    __shared__ float red[8];

    float v[8];
    float m = -1e30f;
    #pragma unroll
    for (int i = 0; i < 8; i++) {
        v[i] = row[tid + i * 256];
        m = fmaxf(m, v[i]);
    }
    #pragma unroll
    for (int o = 16; o > 0; o >>= 1) m = fmaxf(m, __shfl_xor_sync(0xFFFFFFFFu, m, o));
    if ((tid & 31) == 0) red[tid >> 5] = m;
    __syncthreads();
    m = red[0];
    #pragma unroll
    for (int i = 1; i < 8; i++) m = fmaxf(m, red[i]);
    __syncthreads();

    float sum = 0.0f;
    #pragma unroll
    for (int i = 0; i < 8; i++) {
        v[i] = expf(v[i] - m);
        sum += v[i];
    }
    #pragma unroll
    for (int o = 16; o > 0; o >>= 1) sum += __shfl_xor_sync(0xFFFFFFFFu, sum, o);
    if ((tid & 31) == 0) red[tid >> 5] = sum;
    __syncthreads();
    sum = 0.0f;
    #pragma unroll
    for (int i = 0; i < 8; i++) sum += red[i];

    float inv = 1.0f / sum;
    #pragma unroll
    for (int i = 0; i < 8; i++) {
        float f = v[i] * inv;
        bf16 h = __float2bfloat16(f);
        bf16 l = __float2bfloat16(f - __bfloat162float(h));
        rh[tid + i * 256] = h;
        rl[tid + i * 256] = l;
    }
}

// ---------------- launch ----------------
extern "C" void kernel_launch(void* const* d_in, const int* in_sizes, int n_in,
                              void* d_out, int out_size)
{
    const float* x  = (const float*)d_in[0];
    const float* wq = (const float*)d_in[1];
    const float* bq = (const float*)d_in[2];
    const float* wk = (const float*)d_in[3];
    const float* bk = (const float*)d_in[4];
    const float* wv = (const float*)d_in[5];
    const float* bv = (const float*)d_in[6];
    float* out = (float*)d_out;

    bf16 *Xh, *Xl, *Wh, *Wl, *Qh, *Ql, *Kh, *Kl, *Vh, *Vl, *Ph, *Pl;
    float *Sc;
    cudaGetSymbolAddress((void**)&Xh, g_Xhi);  cudaGetSymbolAddress((void**)&Xl, g_Xlo);
    cudaGetSymbolAddress((void**)&Wh, g_Whi);  cudaGetSymbolAddress((void**)&Wl, g_Wlo);
    cudaGetSymbolAddress((void**)&Qh, g_Qhi);  cudaGetSymbolAddress((void**)&Ql, g_Qlo);
    cudaGetSymbolAddress((void**)&Kh, g_Khi);  cudaGetSymbolAddress((void**)&Kl, g_Klo);
    cudaGetSymbolAddress((void**)&Vh, g_Vhi);  cudaGetSymbolAddress((void**)&Vl, g_Vlo);
    cudaGetSymbolAddress((void**)&Sc, g_S);
    cudaGetSymbolAddress((void**)&Ph, g_Phi);  cudaGetSymbolAddress((void**)&Pl, g_Plo);

    cudaFuncSetAttribute(gemm_plain<0>, cudaFuncAttributeMaxDynamicSharedMemorySize, SMEM_GEMM_BYTES);
    cudaFuncSetAttribute(gemm_plain<1>, cudaFuncAttributeMaxDynamicSharedMemorySize, SMEM_GEMM_BYTES);
    cudaFuncSetAttribute(gemm_proj,     cudaFuncAttributeMaxDynamicSharedMemorySize, SMEM_GEMM_BYTES);

    const size_t WN = (size_t)D_DIM * D_DIM;

    // 0) split conversions (x, and W concatenated as [3072][1024])
    split_kernel<<<(M_ROWS * D_DIM / 8 + 255) / 256, 256>>>(x, Xh, Xl, M_ROWS * D_DIM / 8);
    split_kernel<<<(WN / 8 + 255) / 256, 256>>>(wq, Wh + 0 * WN, Wl + 0 * WN, WN / 8);
    split_kernel<<<(WN / 8 + 255) / 256, 256>>>(wk, Wh + 1 * WN, Wl + 1 * WN, WN / 8);
    split_kernel<<<(WN / 8 + 255) / 256, 256>>>(wv, Wh + 2 * WN, Wl + 2 * WN, WN / 8);

    // 1) fused QKV projection + bias + RoPE + split (M=8192, N=3072, K=1024)
    dim3 gP(3 * D_DIM / 256, M_ROWS / 128, 1);
    gemm_proj<<<gP, 256, SMEM_GEMM_BYTES>>>(Xh, Xl, Wh, Wl, bq, bk, bv,
                                            Qh, Ql, Kh, Kl, Vh, Vl);

    // 2) scores = Q @ K^T / 32, batched (M=2048, N=2048, K=1024)
    dim3 gS(S_LEN / 256, S_LEN / 128, B_SZ);
    gemm_plain<0><<<gS, 256, SMEM_GEMM_BYTES>>>(Qh, Ql, Kh, Kl, Sc, S_LEN, D_DIM,
                                                (long long)S_LEN * D_DIM, (long long)S_LEN * D_DIM,
                                                (long long)S_LEN * S_LEN, 0.03125f);

    // 3) softmax + split
    softmax_split_kernel<<<M_ROWS, 256>>>(Sc, Ph, Pl);

    // 4) out = P @ V (V row-major [s][d], NN via ldmatrix.trans), batched
    dim3 gO(D_DIM / 256, S_LEN / 128, B_SZ);
    gemm_plain<1><<<gO, 256, SMEM_GEMM_BYTES>>>(Ph, Pl, Vh, Vl, out, D_DIM, S_LEN,
                                                (long long)S_LEN * S_LEN, (long long)S_LEN * D_DIM,
                                                (long long)S_LEN * D_DIM, 1.0f);
}

// round 8
// speedup vs baseline: 1.6186x; 1.6186x over previous
#include <cuda_runtime.h>
#include <math.h>
#include <stdint.h>

#define B_SZ  4
#define S_LEN 2048
#define D_DIM 1024
#define M_ROWS (B_SZ * S_LEN)   // 8192

// ---------------- scratch (allocation-free: __device__ globals) ----------------
__device__ float g_X [(size_t)M_ROWS * D_DIM];              // tf32-rounded x
__device__ float g_W [(size_t)3 * D_DIM * D_DIM];           // tf32-rounded wq|wk|wv
__device__ float g_Q [(size_t)M_ROWS * D_DIM];              // tf32 (post-rope)
__device__ float g_K [(size_t)M_ROWS * D_DIM];              // tf32 (post-rope)
__device__ float g_Vt[(size_t)D_DIM * M_ROWS];              // tf32, [d][b*S+s]
__device__ float g_S [(size_t)B_SZ * S_LEN * S_LEN];        // scores -> probs(tf32)

// ======================= helpers =======================
__device__ __forceinline__ uint32_t smem_u32(const void* p) {
    uint32_t a;
    asm("{ .reg .u64 t; cvta.to.shared.u64 t, %1; cvt.u32.u64 %0, t; }" : "=r"(a) : "l"(p));
    return a;
}
__device__ __forceinline__ float f2tf(float f) {
    uint32_t r; asm("cvt.rna.tf32.f32 %0, %1;" : "=r"(r) : "f"(f));
    return __uint_as_float(r);
}
__device__ __forceinline__ void ldsm4(uint32_t& r0, uint32_t& r1, uint32_t& r2, uint32_t& r3,
                                      uint32_t addr) {
    asm volatile("ldmatrix.sync.aligned.m8n8.x4.shared.b16 {%0,%1,%2,%3}, [%4];"
                 : "=r"(r0), "=r"(r1), "=r"(r2), "=r"(r3) : "r"(addr));
}
__device__ __forceinline__ void mma_tf32(float& d0, float& d1, float& d2, float& d3,
                                         uint32_t a0, uint32_t a1, uint32_t a2, uint32_t a3,
                                         uint32_t b0, uint32_t b1) {
    asm volatile(
        "mma.sync.aligned.m16n8k8.row.col.f32.tf32.tf32.f32 "
        "{%0,%1,%2,%3},{%4,%5,%6,%7},{%8,%9},{%0,%1,%2,%3};"
        : "+f"(d0), "+f"(d1), "+f"(d2), "+f"(d3)
        : "r"(a0), "r"(a1), "r"(a2), "r"(a3), "r"(b0), "r"(b1));
}
__device__ __forceinline__ void cp16(uint32_t dst, const void* src) {
    asm volatile("cp.async.cg.shared.global [%0], [%1], 16;"
                 :: "r"(dst), "l"(__cvta_generic_to_global(src)) : "memory");
}
#define CP_COMMIT() asm volatile("cp.async.commit_group;" ::: "memory")
#define CP_WAIT2()  asm volatile("cp.async.wait_group 2;" ::: "memory")

// fp32 tile [128 rows][32 cols] = 128B rows, 8x 16B chunks; phys chunk = ch ^ (row&7)
__device__ __forceinline__ uint32_t swz(int row, int ch) {
    return (uint32_t)(row * 128 + ((ch ^ (row & 7)) << 4));
}

// CTA tile 128x128, BK=32, 8 warps (2x4), warp tile 64x32, 2 CTAs/SM
#define TILE_BYTES 16384                    // 128*32*4
#define STAGE_BYTES (2 * TILE_BYTES)        // A + B
#define SMEM_GEMM_BYTES (3 * STAGE_BYTES)   // 98304

// ======================= shared mainloop (NT: A[M,K], B[N,K] via ldB) =======================
__device__ __forceinline__ void issue_stage(
    uint32_t base, const float* Ag, const float* Bg, int K, int ldB, int tid, int c)
{
    const float* Ac = Ag + (long long)c * 32;
    const float* Bc = Bg + (long long)c * 32;
    #pragma unroll
    for (int p = 0; p < 4; p++) {
        int cidx = tid + p * 256;
        int row = cidx >> 3, ch = cidx & 7;
        cp16(base + swz(row, ch), Ac + (long long)row * K + ch * 4);
    }
    #pragma unroll
    for (int p = 0; p < 4; p++) {
        int cidx = tid + p * 256;
        int row = cidx >> 3, ch = cidx & 7;
        cp16(base + TILE_BYTES + swz(row, ch), Bc + (long long)row * ldB + ch * 4);
    }
    CP_COMMIT();
}

__device__ __forceinline__ void gemm_mainloop(
    const float* Ag, const float* Bg, int K, int ldB,
    uint32_t sbase, int tid, float acc[4][4][4])
{
    const int wid = tid >> 5, lane = tid & 31;
    const int warpM = (wid >> 2) * 64, warpN = (wid & 3) * 32;
    const int NC = K >> 5;

    issue_stage(sbase,               Ag, Bg, K, ldB, tid, 0);
    issue_stage(sbase + STAGE_BYTES, Ag, Bg, K, ldB, tid, 1);

    // ldmatrix lane mapping (shared by A and B x4 loads)
    const int tG = lane >> 3, ro = lane & 7;
    const int aRow = ro + ((tG & 1) << 3);      // A: tiles 0/2 -> +0, 1/3 -> +8
    const int aChO = tG >> 1;                   // A: tiles 2,3 -> chunk +1
    const int bRow = ro + ((tG >> 1) << 3);     // B: tiles 2,3 -> +8 rows
    const int bChO = tG & 1;                    // B: tiles 1,3 -> chunk +1

    for (int c = 0; c < NC; c++) {
        if (c + 2 < NC) {
            issue_stage(sbase + ((c + 2) % 3) * STAGE_BYTES, Ag, Bg, K, ldB, tid, c + 2);
        } else {
            CP_COMMIT();
        }
        CP_WAIT2();
        __syncthreads();

        const uint32_t sA = sbase + (c % 3) * STAGE_BYTES;
        const uint32_t sB = sA + TILE_BYTES;

        #pragma unroll
        for (int kkk = 0; kkk < 4; kkk++) {
            // B fragments: 4 n8 tiles -> b[nt][2]
            uint32_t b[4][2];
            {
                int nr = warpN + bRow;
                int ch = 2 * kkk + bChO;
                ldsm4(b[0][0], b[0][1], b[1][0], b[1][1], sB + swz(nr, ch));
                ldsm4(b[2][0], b[2][1], b[3][0], b[3][1], sB + swz(nr + 16, ch));
            }
            #pragma unroll
            for (int mt = 0; mt < 4; mt++) {
                int ar = warpM + mt * 16 + aRow;
                int ch = 2 * kkk + aChO;
                uint32_t a0, a1, a2, a3;
                ldsm4(a0, a1, a2, a3, sA + swz(ar, ch));
                #pragma unroll
                for (int nt = 0; nt < 4; nt++)
                    mma_tf32(acc[mt][nt][0], acc[mt][nt][1], acc[mt][nt][2], acc[mt][nt][3],
                             a0, a1, a2, a3, b[nt][0], b[nt][1]);
            }
        }
        __syncthreads();
    }
}

// ======================= plain GEMM kernel (scores / PV) =======================
__global__ void __launch_bounds__(256, 2) gemm_nt(
    const float* __restrict__ A, const float* __restrict__ B,
    float* __restrict__ C, int N, int K, int ldB,
    long long sA, long long sB, long long sC, float alpha)
{
    extern __shared__ uint32_t sm[];
    const uint32_t sbase = smem_u32(sm);
    const int tid = threadIdx.x, wid = tid >> 5, lane = tid & 31;
    const int bm = blockIdx.y * 128, bn = blockIdx.x * 128;

    const float* Ag = A + blockIdx.z * sA + (long long)bm * K;
    const float* Bg = B + blockIdx.z * sB + (long long)bn * ldB;

    float acc[4][4][4];
    #pragma unroll
    for (int m = 0; m < 4; m++)
        #pragma unroll
        for (int n = 0; n < 4; n++)
            #pragma unroll
            for (int e = 0; e < 4; e++) acc[m][n][e] = 0.0f;

    gemm_mainloop(Ag, Bg, K, ldB, sbase, tid, acc);

    C += blockIdx.z * sC;
    const int warpM = (wid >> 2) * 64, warpN = (wid & 3) * 32;
    const int r = lane >> 2, q = lane & 3;
    #pragma unroll
    for (int mt = 0; mt < 4; mt++) {
        #pragma unroll
        for (int nt = 0; nt < 4; nt++) {
            int row = bm + warpM + mt * 16 + r;
            int col = bn + warpN + nt * 8 + q * 2;
            float2 o0 = make_float2(acc[mt][nt][0] * alpha, acc[mt][nt][1] * alpha);
            float2 o1 = make_float2(acc[mt][nt][2] * alpha, acc[mt][nt][3] * alpha);
            *(float2*)(C + (long long)row * N + col)       = o0;
            *(float2*)(C + (long long)(row + 8) * N + col) = o1;
        }
    }
}

// ======================= fused projection: QKV + bias + RoPE + tf32 round =======================
// Writes Q,K as [row][d] (tf32), V transposed into Vt[d][row] (tf32).
__global__ void __launch_bounds__(256, 2) gemm_proj(
    const float* __restrict__ A, const float* __restrict__ B,
    const float* __restrict__ bq, const float* __restrict__ bk, const float* __restrict__ bv,
    float* __restrict__ Q, float* __restrict__ Kd, float* __restrict__ Vt)
{
    extern __shared__ uint32_t sm[];
    const uint32_t sbase = smem_u32(sm);
    const int tid = threadIdx.x, wid = tid >> 5, lane = tid & 31;
    const int bm = blockIdx.y * 128, bn = blockIdx.x * 128;
    const int K = D_DIM;

    const float* Ag = A + (long long)bm * K;
    const float* Bg = B + (long long)bn * K;

    float acc[4][4][4];
    #pragma unroll
    for (int m = 0; m < 4; m++)
        #pragma unroll
        for (int n = 0; n < 4; n++)
            #pragma unroll
            for (int e = 0; e < 4; e++) acc[m][n][e] = 0.0f;

    gemm_mainloop(Ag, Bg, K, K, sbase, tid, acc);

    const int warpM = (wid >> 2) * 64, warpN = (wid & 3) * 32;
    const int r = lane >> 2, q = lane & 3;
    const int sel = bn >> 10;                   // 0=Q 1=K 2=V (bn multiple of 128)
    const float* bias = (sel == 0) ? bq : (sel == 1) ? bk : bv;

    #pragma unroll
    for (int nt = 0; nt < 4; nt++) {
        int col = bn + warpN + nt * 8 + q * 2;   // even
        int cl  = col & 1023;
        float b0 = bias[cl], b1 = bias[cl + 1];
        float invf = (sel < 2) ? powf(10000.0f, -(float)cl * (1.0f / (float)D_DIM)) : 0.0f;
        #pragma unroll
        for (int mt = 0; mt < 4; mt++) {
            #pragma unroll
            for (int rr = 0; rr < 2; rr++) {
                int row = bm + warpM + mt * 16 + r + rr * 8;
                float v0 = acc[mt][nt][rr * 2 + 0] + b0;
                float v1 = acc[mt][nt][rr * 2 + 1] + b1;
                if (sel < 2) {
                    int s = row & (S_LEN - 1);
                    float sn, cs;
                    sincosf((float)s * invf, &sn, &cs);
                    float t0 = v0 * cs - v1 * sn;
                    float t1 = v0 * sn + v1 * cs;
                    v0 = t0; v1 = t1;
                }
                v0 = f2tf(v0); v1 = f2tf(v1);
                if (sel == 2) {
                    Vt[(long long)cl * M_ROWS + row]       = v0;
                    Vt[(long long)(cl + 1) * M_ROWS + row] = v1;
                } else {
                    float* O = (sel == 0) ? Q : Kd;
                    *(float2*)(O + (long long)row * D_DIM + cl) = make_float2(v0, v1);
                }
            }
        }
    }
}

// ---------------- fp32 -> tf32 rounding (vectorized) ----------------
__global__ void __launch_bounds__(256) round_kernel(const float4* __restrict__ in,
                                                    float4* __restrict__ out, int n4)
{
    int i = blockIdx.x * 256 + threadIdx.x;
    if (i >= n4) return;
    float4 v = in[i];
    out[i] = make_float4(f2tf(v.x), f2tf(v.y), f2tf(v.z), f2tf(v.w));
}

// ---------------- row softmax over S_LEN, in place, tf32-rounded output ----------------
__global__ void __launch_bounds__(256) softmax_kernel(float* __restrict__ P)
{
    float* row = P + (long long)blockIdx.x * S_LEN;
    const int tid = threadIdx.x;
    __shared__ float red[8];

    float v[8];
    float m = -1e30f;
    #pragma unroll
    for (int i = 0; i < 8; i++) {
        v[i] = row[tid + i * 256];
        m = fmaxf(m, v[i]);
    }
    #pragma unroll
    for (int o = 16; o > 0; o >>= 1) m = fmaxf(m, __shfl_xor_sync(0xFFFFFFFFu, m, o));
    if ((tid & 31) == 0) red[tid >> 5] = m;
    __syncthreads();
    m = red[0];
    #pragma unroll
    for (int i = 1; i < 8; i++) m = fmaxf(m, red[i]);
    __syncthreads();

    float sum = 0.0f;
    #pragma unroll
    for (int i = 0; i < 8; i++) {
        v[i] = expf(v[i] - m);
        sum += v[i];
    }
    #pragma unroll
    for (int o = 16; o > 0; o >>= 1) sum += __shfl_xor_sync(0xFFFFFFFFu, sum, o);
    if ((tid & 31) == 0) red[tid >> 5] = sum;
    __syncthreads();
    sum = 0.0f;
    #pragma unroll
    for (int i = 0; i < 8; i++) sum += red[i];

    float inv = 1.0f / sum;
    #pragma unroll
    for (int i = 0; i < 8; i++) row[tid + i * 256] = f2tf(v[i] * inv);
}

// ---------------- launch ----------------
extern "C" void kernel_launch(void* const* d_in, const int* in_sizes, int n_in,
                              void* d_out, int out_size)
{
    const float* x  = (const float*)d_in[0];
    const float* wq = (const float*)d_in[1];
    const float* bq = (const float*)d_in[2];
    const float* wk = (const float*)d_in[3];
    const float* bk = (const float*)d_in[4];
    const float* wv = (const float*)d_in[5];
    const float* bv = (const float*)d_in[6];
    float* out = (float*)d_out;

    float *X, *W, *Q, *K, *Vt, *Sc;
    cudaGetSymbolAddress((void**)&X,  g_X);
    cudaGetSymbolAddress((void**)&W,  g_W);
    cudaGetSymbolAddress((void**)&Q,  g_Q);
    cudaGetSymbolAddress((void**)&K,  g_K);
    cudaGetSymbolAddress((void**)&Vt, g_Vt);
    cudaGetSymbolAddress((void**)&Sc, g_S);

    cudaFuncSetAttribute(gemm_nt,   cudaFuncAttributeMaxDynamicSharedMemorySize, SMEM_GEMM_BYTES);
    cudaFuncSetAttribute(gemm_proj, cudaFuncAttributeMaxDynamicSharedMemorySize, SMEM_GEMM_BYTES);

    const size_t WN = (size_t)D_DIM * D_DIM;

    // 0) tf32-round x and weights (W concatenated as [3072][1024])
    round_kernel<<<(M_ROWS * D_DIM / 4 + 255) / 256, 256>>>((const float4*)x, (float4*)X, M_ROWS * D_DIM / 4);
    round_kernel<<<(WN / 4 + 255) / 256, 256>>>((const float4*)wq, (float4*)(W + 0 * WN), WN / 4);
    round_kernel<<<(WN / 4 + 255) / 256, 256>>>((const float4*)wk, (float4*)(W + 1 * WN), WN / 4);
    round_kernel<<<(WN / 4 + 255) / 256, 256>>>((const float4*)wv, (float4*)(W + 2 * WN), WN / 4);

    // 1) fused QKV projection + bias + RoPE + tf32 round (M=8192, N=3072, K=1024)
    dim3 gP(3 * D_DIM / 128, M_ROWS / 128, 1);
    gemm_proj<<<gP, 256, SMEM_GEMM_BYTES>>>(X, W, bq, bk, bv, Q, K, Vt);

    // 2) scores = Q @ K^T / 32, batched (M=2048, N=2048, K=1024)
    dim3 gS(S_LEN / 128, S_LEN / 128, B_SZ);
    gemm_nt<<<gS, 256, SMEM_GEMM_BYTES>>>(Q, K, Sc, S_LEN, D_DIM, D_DIM,
                                          (long long)S_LEN * D_DIM, (long long)S_LEN * D_DIM,
                                          (long long)S_LEN * S_LEN, 0.03125f);

    // 3) softmax (in place, tf32-rounded)
    softmax_kernel<<<M_ROWS, 256>>>(Sc);

    // 4) out = P @ Vt^T, batched (M=2048, N=1024, K=2048); Vt rows stride M_ROWS, batch offset in k
    dim3 gO(D_DIM / 128, S_LEN / 128, B_SZ);
    gemm_nt<<<gO, 256, SMEM_GEMM_BYTES>>>(Sc, Vt, out, D_DIM, S_LEN, M_ROWS,
                                          (long long)S_LEN * S_LEN, (long long)S_LEN,
                                          (long long)S_LEN * D_DIM, 1.0f);
}

// round 10
// speedup vs baseline: 2.6552x; 1.6404x over previous
#include <cuda_runtime.h>
#include <cuda_fp16.h>
#include <math.h>
#include <stdint.h>

#define B_SZ  4
#define S_LEN 2048
#define D_DIM 1024
#define M_ROWS (B_SZ * S_LEN)   // 8192

// ---------------- scratch (allocation-free: __device__ globals) ----------------
__device__ __half g_X16[(size_t)M_ROWS * D_DIM];              // fp16(x)
__device__ __half g_W16[(size_t)3 * D_DIM * D_DIM];           // fp16(wq|wk|wv) [3072][1024]
__device__ __half g_Q16[(size_t)M_ROWS * D_DIM];              // fp16 post-rope
__device__ __half g_K16[(size_t)M_ROWS * D_DIM];
__device__ __half g_V16[(size_t)M_ROWS * D_DIM];              // row-major [b*S+s][d]
__device__ float  g_S  [(size_t)B_SZ * S_LEN * S_LEN];        // fp32 scores
__device__ __half g_P16[(size_t)B_SZ * S_LEN * S_LEN];        // fp16 probs

// ======================= helpers =======================
__device__ __forceinline__ uint32_t smem_u32(const void* p) {
    uint32_t a;
    asm("{ .reg .u64 t; cvta.to.shared.u64 t, %1; cvt.u32.u64 %0, t; }" : "=r"(a) : "l"(p));
    return a;
}
__device__ __forceinline__ uint32_t pack_h2(float a, float b) {
    __half2 h = __floats2half2_rn(a, b);
    return *(uint32_t*)&h;
}
__device__ __forceinline__ void ldsm4(uint32_t& r0, uint32_t& r1, uint32_t& r2, uint32_t& r3,
                                      uint32_t addr) {
    asm volatile("ldmatrix.sync.aligned.m8n8.x4.shared.b16 {%0,%1,%2,%3}, [%4];"
                 : "=r"(r0), "=r"(r1), "=r"(r2), "=r"(r3) : "r"(addr));
}
__device__ __forceinline__ void ldsm4t(uint32_t& r0, uint32_t& r1, uint32_t& r2, uint32_t& r3,
                                       uint32_t addr) {
    asm volatile("ldmatrix.sync.aligned.m8n8.x4.trans.shared.b16 {%0,%1,%2,%3}, [%4];"
                 : "=r"(r0), "=r"(r1), "=r"(r2), "=r"(r3) : "r"(addr));
}
__device__ __forceinline__ void mma16816(float& d0, float& d1, float& d2, float& d3,
                                         uint32_t a0, uint32_t a1, uint32_t a2, uint32_t a3,
                                         uint32_t b0, uint32_t b1) {
    asm volatile(
        "mma.sync.aligned.m16n8k16.row.col.f32.f16.f16.f32 "
        "{%0,%1,%2,%3},{%4,%5,%6,%7},{%8,%9},{%0,%1,%2,%3};"
        : "+f"(d0), "+f"(d1), "+f"(d2), "+f"(d3)
        : "r"(a0), "r"(a1), "r"(a2), "r"(a3), "r"(b0), "r"(b1));
}
__device__ __forceinline__ void cp16(uint32_t dst, const void* src) {
    asm volatile("cp.async.cg.shared.global [%0], [%1], 16;"
                 :: "r"(dst), "l"(__cvta_generic_to_global(src)) : "memory");
}
#define CP_COMMIT() asm volatile("cp.async.commit_group;" ::: "memory")
#define CP_WAIT2()  asm volatile("cp.async.wait_group 2;" ::: "memory")

// A / NT-B tiles: [128 rows][32 fp16] = 64B rows; chunk c(0..3) ^= (row>>1)&3
__device__ __forceinline__ uint32_t swp(int row, int chunk) {
    return (uint32_t)(row * 64 + ((chunk ^ ((row >> 1) & 3)) << 4));
}
// NN-B tile: [32 k-rows][128 n-cols] fp16 = 256B rows; chunk c(0..15) ^= k&7
__device__ __forceinline__ uint32_t swb(int k, int chunk) {
    return (uint32_t)(k * 256 + ((chunk ^ (k & 7)) << 4));
}

// CTA tile 128x128, BK=32, 8 warps (2x4), warp tile 64x32, 2 CTAs/SM
#define TILE_HB 8192                        // 128*32*2 (or 32*128*2)
#define STAGE_BYTES (2 * TILE_HB)           // A + B
#define SMEM_GEMM_BYTES (3 * STAGE_BYTES)   // 49152

// ======================= shared mainloop =======================
// BMODE 0: B = [N,K] row-major (NT).  BMODE 1: B = [K,N] row-major (NN, ldmatrix.trans)
template<int BMODE>
__device__ __forceinline__ void issue_stage(
    uint32_t base, const __half* Ag, const __half* Bg, int K, int ldB, int tid, int c)
{
    const __half* Ac = Ag + (long long)c * 32;
    #pragma unroll
    for (int p = 0; p < 2; p++) {
        int cidx = tid + p * 256;
        int row = cidx >> 2, ch = cidx & 3;
        cp16(base + swp(row, ch), Ac + (long long)row * K + ch * 8);
    }
    if (BMODE == 0) {
        const __half* Bc = Bg + (long long)c * 32;
        #pragma unroll
        for (int p = 0; p < 2; p++) {
            int cidx = tid + p * 256;
            int row = cidx >> 2, ch = cidx & 3;
            cp16(base + TILE_HB + swp(row, ch), Bc + (long long)row * K + ch * 8);
        }
    } else {
        const __half* Bc = Bg + (long long)c * 32 * ldB;
        #pragma unroll
        for (int p = 0; p < 2; p++) {
            int cidx = tid + p * 256;
            int k = cidx >> 4, ch = cidx & 15;
            cp16(base + TILE_HB + swb(k, ch), Bc + (long long)k * ldB + ch * 8);
        }
    }
    CP_COMMIT();
}

template<int BMODE>
__device__ __forceinline__ void gemm_mainloop(
    const __half* Ag, const __half* Bg, int K, int ldB,
    uint32_t sbase, int tid, float acc[4][4][4])
{
    const int wid = tid >> 5, lane = tid & 31;
    const int warpM = (wid >> 2) * 64, warpN = (wid & 3) * 32;
    const int NC = K >> 5;

    issue_stage<BMODE>(sbase,               Ag, Bg, K, ldB, tid, 0);
    issue_stage<BMODE>(sbase + STAGE_BYTES, Ag, Bg, K, ldB, tid, 1);

    // lane mappings
    const int laA = lane & 15, lcA = lane >> 4;          // A / NT-B
    const int laB = (lane & 7) + ((lane & 16) >> 1);
    const int lcB = (lane >> 3) & 1;
    const int lrT = lane & 7, gT = lane >> 3;            // NN-B trans

    for (int c = 0; c < NC; c++) {
        if (c + 2 < NC) {
            issue_stage<BMODE>(sbase + ((c + 2) % 3) * STAGE_BYTES, Ag, Bg, K, ldB, tid, c + 2);
        } else {
            CP_COMMIT();
        }
        CP_WAIT2();
        __syncthreads();

        const uint32_t sA = sbase + (c % 3) * STAGE_BYTES;
        const uint32_t sB = sA + TILE_HB;

        #pragma unroll
        for (int kk = 0; kk < 2; kk++) {
            uint32_t b[4][2];
            if (BMODE == 0) {
                #pragma unroll
                for (int g = 0; g < 2; g++) {
                    int rB = warpN + g * 16 + laB;
                    uint32_t off = swp(rB, 2 * kk + lcB);
                    ldsm4(b[2*g][0], b[2*g][1], b[2*g+1][0], b[2*g+1][1], sB + off);
                }
            } else {
                int k = kk * 16 + (gT & 1) * 8 + lrT;
                int cb = (warpN >> 3) + (gT >> 1);
                ldsm4t(b[0][0], b[0][1], b[1][0], b[1][1], sB + swb(k, cb));
                ldsm4t(b[2][0], b[2][1], b[3][0], b[3][1], sB + swb(k, cb + 2));
            }
            #pragma unroll
            for (int mt = 0; mt < 4; mt++) {
                int rA = warpM + mt * 16 + laA;
                uint32_t off = swp(rA, 2 * kk + lcA);
                uint32_t a0, a1, a2, a3;
                ldsm4(a0, a1, a2, a3, sA + off);
                #pragma unroll
                for (int nt = 0; nt < 4; nt++)
                    mma16816(acc[mt][nt][0], acc[mt][nt][1], acc[mt][nt][2], acc[mt][nt][3],
                             a0, a1, a2, a3, b[nt][0], b[nt][1]);
            }
        }
        __syncthreads();
    }
}

// ======================= plain GEMM kernel (scores / PV) =======================
template<int BMODE>
__global__ void __launch_bounds__(256, 2) gemm_plain(
    const __half* __restrict__ A, const __half* __restrict__ B,
    float* __restrict__ C, int N, int K,
    long long sA, long long sB, long long sC, float alpha)
{
    extern __shared__ uint32_t sm[];
    const uint32_t sbase = smem_u32(sm);
    const int tid = threadIdx.x, wid = tid >> 5, lane = tid & 31;
    const int bm = blockIdx.y * 128, bn = blockIdx.x * 128;

    const __half* Ag = A + blockIdx.z * sA + (long long)bm * K;
    const __half* Bg;
    if (BMODE == 0) Bg = B + blockIdx.z * sB + (long long)bn * K;
    else            Bg = B + blockIdx.z * sB + bn;

    float acc[4][4][4];
    #pragma unroll
    for (int m = 0; m < 4; m++)
        #pragma unroll
        for (int n = 0; n < 4; n++)
            #pragma unroll
            for (int e = 0; e < 4; e++) acc[m][n][e] = 0.0f;

    gemm_mainloop<BMODE>(Ag, Bg, K, (BMODE ? N : K), sbase, tid, acc);

    C += blockIdx.z * sC;
    const int warpM = (wid >> 2) * 64, warpN = (wid & 3) * 32;
    const int r = lane >> 2, q = lane & 3;
    #pragma unroll
    for (int mt = 0; mt < 4; mt++) {
        #pragma unroll
        for (int nt = 0; nt < 4; nt++) {
            int row = bm + warpM + mt * 16 + r;
            int col = bn + warpN + nt * 8 + q * 2;
            float2 o0 = make_float2(acc[mt][nt][0] * alpha, acc[mt][nt][1] * alpha);
            float2 o1 = make_float2(acc[mt][nt][2] * alpha, acc[mt][nt][3] * alpha);
            *(float2*)(C + (long long)row * N + col)       = o0;
            *(float2*)(C + (long long)(row + 8) * N + col) = o1;
        }
    }
}

// ======================= fused projection: QKV + bias + RoPE -> fp16 =======================
__global__ void __launch_bounds__(256, 2) gemm_proj(
    const __half* __restrict__ A, const __half* __restrict__ B,
    const float* __restrict__ bq, const float* __restrict__ bk, const float* __restrict__ bv,
    __half* __restrict__ Q, __half* __restrict__ Kd, __half* __restrict__ V)
{
    extern __shared__ uint32_t sm[];
    const uint32_t sbase = smem_u32(sm);
    const int tid = threadIdx.x, wid = tid >> 5, lane = tid & 31;
    const int bm = blockIdx.y * 128, bn = blockIdx.x * 128;
    const int K = D_DIM;

    const __half* Ag = A + (long long)bm * K;
    const __half* Bg = B + (long long)bn * K;

    float acc[4][4][4];
    #pragma unroll
    for (int m = 0; m < 4; m++)
        #pragma unroll
        for (int n = 0; n < 4; n++)
            #pragma unroll
            for (int e = 0; e < 4; e++) acc[m][n][e] = 0.0f;

    gemm_mainloop<0>(Ag, Bg, K, K, sbase, tid, acc);

    const int warpM = (wid >> 2) * 64, warpN = (wid & 3) * 32;
    const int r = lane >> 2, q = lane & 3;
    const int sel = bn >> 10;                   // 0=Q 1=K 2=V
    const float* bias = (sel == 0) ? bq : (sel == 1) ? bk : bv;
    uint32_t* O = (uint32_t*)((sel == 0) ? Q : (sel == 1) ? Kd : V);

    #pragma unroll
    for (int nt = 0; nt < 4; nt++) {
        int col = bn + warpN + nt * 8 + q * 2;   // even
        int cl  = col & 1023;
        float b0 = bias[cl], b1 = bias[cl + 1];
        float invf = (sel < 2) ? powf(10000.0f, -(float)cl * (1.0f / (float)D_DIM)) : 0.0f;
        #pragma unroll
        for (int mt = 0; mt < 4; mt++) {
            #pragma unroll
            for (int rr = 0; rr < 2; rr++) {
                int row = bm + warpM + mt * 16 + r + rr * 8;
                float v0 = acc[mt][nt][rr * 2 + 0] + b0;
                float v1 = acc[mt][nt][rr * 2 + 1] + b1;
                if (sel < 2) {
                    int s = row & (S_LEN - 1);
                    float sn, cs;
                    sincosf((float)s * invf, &sn, &cs);
                    float t0 = v0 * cs - v1 * sn;
                    float t1 = v0 * sn + v1 * cs;
                    v0 = t0; v1 = t1;
                }
                O[(long long)row * (D_DIM / 2) + (cl >> 1)] = pack_h2(v0, v1);
            }
        }
    }
}

// ---------------- fp32 -> fp16 conversion (8 elems/thread) ----------------
__global__ void __launch_bounds__(256) cvt_kernel(const float* __restrict__ in,
                                                  __half* __restrict__ out, int n8)
{
    int i = blockIdx.x * 256 + threadIdx.x;
    if (i >= n8) return;
    const float4* in4 = (const float4*)in;
    float4 v0 = in4[2 * i], v1 = in4[2 * i + 1];
    uint4 o;
    o.x = pack_h2(v0.x, v0.y);
    o.y = pack_h2(v0.z, v0.w);
    o.z = pack_h2(v1.x, v1.y);
    o.w = pack_h2(v1.z, v1.w);
    ((uint4*)out)[i] = o;
}

// ---------------- row softmax over S_LEN, fp32 in -> fp16 out ----------------
__global__ void __launch_bounds__(256) softmax_kernel(
    const float* __restrict__ P, __half* __restrict__ P16)
{
    const float* row = P + (long long)blockIdx.x * S_LEN;
    __half* ro = P16 + (long long)blockIdx.x * S_LEN;
    const int tid = threadIdx.x;
    __shared__ float red[8];

    float v[8];
    float m = -1e30f;
    #pragma unroll
    for (int i = 0; i < 8; i++) {
        v[i] = row[tid + i * 256];
        m = fmaxf(m, v[i]);
    }
    #pragma unroll
    for (int o = 16; o > 0; o >>= 1) m = fmaxf(m, __shfl_xor_sync(0xFFFFFFFFu, m, o));
    if ((tid & 31) == 0) red[tid >> 5] = m;
    __syncthreads();
    m = red[0];
    #pragma unroll
    for (int i = 1; i < 8; i++) m = fmaxf(m, red[i]);
    __syncthreads();

    float sum = 0.0f;
    #pragma unroll
    for (int i = 0; i < 8; i++) {
        v[i] = expf(v[i] - m);
        sum += v[i];
    }
    #pragma unroll
    for (int o = 16; o > 0; o >>= 1) sum += __shfl_xor_sync(0xFFFFFFFFu, sum, o);
    if ((tid & 31) == 0) red[tid >> 5] = sum;
    __syncthreads();
    sum = 0.0f;
    #pragma unroll
    for (int i = 0; i < 8; i++) sum += red[i];

    float inv = 1.0f / sum;
    #pragma unroll
    for (int i = 0; i < 8; i++) ro[tid + i * 256] = __float2half(v[i] * inv);
}

// ---------------- launch ----------------
extern "C" void kernel_launch(void* const* d_in, const int* in_sizes, int n_in,
                              void* d_out, int out_size)
{
    const float* x  = (const float*)d_in[0];
    const float* wq = (const float*)d_in[1];
    const float* bq = (const float*)d_in[2];
    const float* wk = (const float*)d_in[3];
    const float* bk = (const float*)d_in[4];
    const float* wv = (const float*)d_in[5];
    const float* bv = (const float*)d_in[6];
    float* out = (float*)d_out;

    __half *X, *W, *Q, *K, *V, *P16;
    float *Sc;
    cudaGetSymbolAddress((void**)&X,   g_X16);
    cudaGetSymbolAddress((void**)&W,   g_W16);
    cudaGetSymbolAddress((void**)&Q,   g_Q16);
    cudaGetSymbolAddress((void**)&K,   g_K16);
    cudaGetSymbolAddress((void**)&V,   g_V16);
    cudaGetSymbolAddress((void**)&Sc,  g_S);
    cudaGetSymbolAddress((void**)&P16, g_P16);

    cudaFuncSetAttribute(gemm_plain<0>, cudaFuncAttributeMaxDynamicSharedMemorySize, SMEM_GEMM_BYTES);
    cudaFuncSetAttribute(gemm_plain<1>, cudaFuncAttributeMaxDynamicSharedMemorySize, SMEM_GEMM_BYTES);
    cudaFuncSetAttribute(gemm_proj,     cudaFuncAttributeMaxDynamicSharedMemorySize, SMEM_GEMM_BYTES);

    const size_t WN = (size_t)D_DIM * D_DIM;

    // 0) fp32 -> fp16 conversions
    cvt_kernel<<<(M_ROWS * D_DIM / 8 + 255) / 256, 256>>>(x, X, M_ROWS * D_DIM / 8);
    cvt_kernel<<<(WN / 8 + 255) / 256, 256>>>(wq, W + 0 * WN, WN / 8);
    cvt_kernel<<<(WN / 8 + 255) / 256, 256>>>(wk, W + 1 * WN, WN / 8);
    cvt_kernel<<<(WN / 8 + 255) / 256, 256>>>(wv, W + 2 * WN, WN / 8);

    // 1) fused QKV projection + bias + RoPE (M=8192, N=3072, K=1024)
    dim3 gP(3 * D_DIM / 128, M_ROWS / 128, 1);
    gemm_proj<<<gP, 256, SMEM_GEMM_BYTES>>>(X, W, bq, bk, bv, Q, K, V);

    // 2) scores = Q @ K^T / 32, batched (M=2048, N=2048, K=1024)
    dim3 gS(S_LEN / 128, S_LEN / 128, B_SZ);
    gemm_plain<0><<<gS, 256, SMEM_GEMM_BYTES>>>(Q, K, Sc, S_LEN, D_DIM,
                                                (long long)S_LEN * D_DIM, (long long)S_LEN * D_DIM,
                                                (long long)S_LEN * S_LEN, 0.03125f);

    // 3) softmax -> fp16
    softmax_kernel<<<M_ROWS, 256>>>(Sc, P16);

    // 4) out = P @ V (V row-major [s][d], NN via ldmatrix.trans), batched
    dim3 gO(D_DIM / 128, S_LEN / 128, B_SZ);
    gemm_plain<1><<<gO, 256, SMEM_GEMM_BYTES>>>(P16, V, out, D_DIM, S_LEN,
                                                (long long)S_LEN * S_LEN, (long long)S_LEN * D_DIM,
                                                (long long)S_LEN * D_DIM, 1.0f);
}

// round 11
// speedup vs baseline: 3.0248x; 1.1392x over previous
#include <cuda_runtime.h>
#include <cuda_fp16.h>
#include <math.h>
#include <stdint.h>

#define B_SZ  4
#define S_LEN 2048
#define D_DIM 1024
#define M_ROWS (B_SZ * S_LEN)   // 8192

// ---------------- scratch (allocation-free: __device__ globals) ----------------
__device__ __half g_X16[(size_t)M_ROWS * D_DIM];              // fp16(x)
__device__ __half g_W16[(size_t)3 * D_DIM * D_DIM];           // fp16(wq|wk|wv) [3072][1024]
__device__ __half g_Q16[(size_t)M_ROWS * D_DIM];              // fp16 post-rope
__device__ __half g_K16[(size_t)M_ROWS * D_DIM];
__device__ __half g_V16[(size_t)M_ROWS * D_DIM];              // row-major [b*S+s][d]
__device__ float  g_S  [(size_t)B_SZ * S_LEN * S_LEN];        // fp32 scores
__device__ __half g_P16[(size_t)B_SZ * S_LEN * S_LEN];        // fp16 probs

// ======================= helpers =======================
__device__ __forceinline__ uint32_t smem_u32(const void* p) {
    uint32_t a;
    asm("{ .reg .u64 t; cvta.to.shared.u64 t, %1; cvt.u32.u64 %0, t; }" : "=r"(a) : "l"(p));
    return a;
}
__device__ __forceinline__ uint32_t pack_h2(float a, float b) {
    __half2 h = __floats2half2_rn(a, b);
    return *(uint32_t*)&h;
}
__device__ __forceinline__ void ldsm4(uint32_t& r0, uint32_t& r1, uint32_t& r2, uint32_t& r3,
                                      uint32_t addr) {
    asm volatile("ldmatrix.sync.aligned.m8n8.x4.shared.b16 {%0,%1,%2,%3}, [%4];"
                 : "=r"(r0), "=r"(r1), "=r"(r2), "=r"(r3) : "r"(addr));
}
__device__ __forceinline__ void ldsm4t(uint32_t& r0, uint32_t& r1, uint32_t& r2, uint32_t& r3,
                                       uint32_t addr) {
    asm volatile("ldmatrix.sync.aligned.m8n8.x4.trans.shared.b16 {%0,%1,%2,%3}, [%4];"
                 : "=r"(r0), "=r"(r1), "=r"(r2), "=r"(r3) : "r"(addr));
}
__device__ __forceinline__ void mma16816(float& d0, float& d1, float& d2, float& d3,
                                         uint32_t a0, uint32_t a1, uint32_t a2, uint32_t a3,
                                         uint32_t b0, uint32_t b1) {
    asm volatile(
        "mma.sync.aligned.m16n8k16.row.col.f32.f16.f16.f32 "
        "{%0,%1,%2,%3},{%4,%5,%6,%7},{%8,%9},{%0,%1,%2,%3};"
        : "+f"(d0), "+f"(d1), "+f"(d2), "+f"(d3)
        : "r"(a0), "r"(a1), "r"(a2), "r"(a3), "r"(b0), "r"(b1));
}
__device__ __forceinline__ void cp16(uint32_t dst, const void* src) {
    asm volatile("cp.async.cg.shared.global [%0], [%1], 16;"
                 :: "r"(dst), "l"(__cvta_generic_to_global(src)) : "memory");
}
#define CP_COMMIT() asm volatile("cp.async.commit_group;" ::: "memory")
#define CP_WAIT2()  asm volatile("cp.async.wait_group 2;" ::: "memory")

// A / NT-B tiles: [128 rows][64 fp16] = 128B rows, 8x 16B chunks; phys chunk = ch ^ (row&7)
__device__ __forceinline__ uint32_t swp(int row, int chunk) {
    return (uint32_t)(row * 128 + ((chunk ^ (row & 7)) << 4));
}
// NN-B tile: [64 k-rows][128 n-cols] fp16 = 256B rows; chunk c(0..15) ^= k&7
__device__ __forceinline__ uint32_t swb(int k, int chunk) {
    return (uint32_t)(k * 256 + ((chunk ^ (k & 7)) << 4));
}

// CTA tile 128x128, BK=64, 8 warps (2x4), warp tile 64x32, 2 CTAs/SM
#define TILE_HB 16384                       // 128*64*2 (or 64*128*2)
#define STAGE_BYTES (2 * TILE_HB)           // A + B
#define SMEM_GEMM_BYTES (3 * STAGE_BYTES)   // 98304

// ======================= shared mainloop =======================
// BMODE 0: B = [N,K] row-major (NT).  BMODE 1: B = [K,N] row-major (NN, ldmatrix.trans)
template<int BMODE>
__device__ __forceinline__ void issue_stage(
    uint32_t base, const __half* Ag, const __half* Bg, int K, int ldB, int tid, int c)
{
    const __half* Ac = Ag + (long long)c * 64;
    #pragma unroll
    for (int p = 0; p < 4; p++) {
        int cidx = tid + p * 256;                  // 0..1023
        int row = cidx >> 3, ch = cidx & 7;
        cp16(base + swp(row, ch), Ac + (long long)row * K + ch * 8);
    }
    if (BMODE == 0) {
        const __half* Bc = Bg + (long long)c * 64;
        #pragma unroll
        for (int p = 0; p < 4; p++) {
            int cidx = tid + p * 256;
            int row = cidx >> 3, ch = cidx & 7;
            cp16(base + TILE_HB + swp(row, ch), Bc + (long long)row * K + ch * 8);
        }
    } else {
        const __half* Bc = Bg + (long long)c * 64 * ldB;
        #pragma unroll
        for (int p = 0; p < 4; p++) {
            int cidx = tid + p * 256;
            int k = cidx >> 4, ch = cidx & 15;
            cp16(base + TILE_HB + swb(k, ch), Bc + (long long)k * ldB + ch * 8);
        }
    }
    CP_COMMIT();
}

template<int BMODE>
__device__ __forceinline__ void gemm_mainloop(
    const __half* Ag, const __half* Bg, int K, int ldB,
    uint32_t sbase, int tid, float acc[4][4][4])
{
    const int wid = tid >> 5, lane = tid & 31;
    const int warpM = (wid >> 2) * 64, warpN = (wid & 3) * 32;
    const int NC = K >> 6;

    issue_stage<BMODE>(sbase,               Ag, Bg, K, ldB, tid, 0);
    issue_stage<BMODE>(sbase + STAGE_BYTES, Ag, Bg, K, ldB, tid, 1);

    // lane mappings
    const int laA = lane & 15, lcA = lane >> 4;          // A / NT-B
    const int laB = (lane & 7) + ((lane & 16) >> 1);
    const int lcB = (lane >> 3) & 1;
    const int lrT = lane & 7, gT = lane >> 3;            // NN-B trans

    for (int c = 0; c < NC; c++) {
        if (c + 2 < NC) {
            issue_stage<BMODE>(sbase + ((c + 2) % 3) * STAGE_BYTES, Ag, Bg, K, ldB, tid, c + 2);
        } else {
            CP_COMMIT();
        }
        CP_WAIT2();
        __syncthreads();

        const uint32_t sA = sbase + (c % 3) * STAGE_BYTES;
        const uint32_t sB = sA + TILE_HB;

        #pragma unroll
        for (int kk = 0; kk < 4; kk++) {
            uint32_t b[4][2];
            if (BMODE == 0) {
                #pragma unroll
                for (int g = 0; g < 2; g++) {
                    int rB = warpN + g * 16 + laB;
                    uint32_t off = swp(rB, 2 * kk + lcB);
                    ldsm4(b[2*g][0], b[2*g][1], b[2*g+1][0], b[2*g+1][1], sB + off);
                }
            } else {
                int k = kk * 16 + (gT & 1) * 8 + lrT;
                int cb = (warpN >> 3) + (gT >> 1);
                ldsm4t(b[0][0], b[0][1], b[1][0], b[1][1], sB + swb(k, cb));
                ldsm4t(b[2][0], b[2][1], b[3][0], b[3][1], sB + swb(k, cb + 2));
            }
            #pragma unroll
            for (int mt = 0; mt < 4; mt++) {
                int rA = warpM + mt * 16 + laA;
                uint32_t off = swp(rA, 2 * kk + lcA);
                uint32_t a0, a1, a2, a3;
                ldsm4(a0, a1, a2, a3, sA + off);
                #pragma unroll
                for (int nt = 0; nt < 4; nt++)
                    mma16816(acc[mt][nt][0], acc[mt][nt][1], acc[mt][nt][2], acc[mt][nt][3],
                             a0, a1, a2, a3, b[nt][0], b[nt][1]);
            }
        }
        __syncthreads();
    }
}

// ======================= plain GEMM kernel (scores / PV) =======================
template<int BMODE>
__global__ void __launch_bounds__(256, 2) gemm_plain(
    const __half* __restrict__ A, const __half* __restrict__ B,
    float* __restrict__ C, int N, int K,
    long long sA, long long sB, long long sC, float alpha)
{
    extern __shared__ uint32_t sm[];
    const uint32_t sbase = smem_u32(sm);
    const int tid = threadIdx.x, wid = tid >> 5, lane = tid & 31;
    const int bm = blockIdx.y * 128, bn = blockIdx.x * 128;

    const __half* Ag = A + blockIdx.z * sA + (long long)bm * K;
    const __half* Bg;
    if (BMODE == 0) Bg = B + blockIdx.z * sB + (long long)bn * K;
    else            Bg = B + blockIdx.z * sB + bn;

    float acc[4][4][4];
    #pragma unroll
    for (int m = 0; m < 4; m++)
        #pragma unroll
        for (int n = 0; n < 4; n++)
            #pragma unroll
            for (int e = 0; e < 4; e++) acc[m][n][e] = 0.0f;

    gemm_mainloop<BMODE>(Ag, Bg, K, (BMODE ? N : K), sbase, tid, acc);

    C += blockIdx.z * sC;
    const int warpM = (wid >> 2) * 64, warpN = (wid & 3) * 32;
    const int r = lane >> 2, q = lane & 3;
    #pragma unroll
    for (int mt = 0; mt < 4; mt++) {
        #pragma unroll
        for (int nt = 0; nt < 4; nt++) {
            int row = bm + warpM + mt * 16 + r;
            int col = bn + warpN + nt * 8 + q * 2;
            float2 o0 = make_float2(acc[mt][nt][0] * alpha, acc[mt][nt][1] * alpha);
            float2 o1 = make_float2(acc[mt][nt][2] * alpha, acc[mt][nt][3] * alpha);
            *(float2*)(C + (long long)row * N + col)       = o0;
            *(float2*)(C + (long long)(row + 8) * N + col) = o1;
        }
    }
}

// ======================= fused projection: QKV + bias + RoPE -> fp16 =======================
__global__ void __launch_bounds__(256, 2) gemm_proj(
    const __half* __restrict__ A, const __half* __restrict__ B,
    const float* __restrict__ bq, const float* __restrict__ bk, const float* __restrict__ bv,
    __half* __restrict__ Q, __half* __restrict__ Kd, __half* __restrict__ V)
{
    extern __shared__ uint32_t sm[];
    const uint32_t sbase = smem_u32(sm);
    const int tid = threadIdx.x, wid = tid >> 5, lane = tid & 31;
    const int bm = blockIdx.y * 128, bn = blockIdx.x * 128;
    const int K = D_DIM;

    const __half* Ag = A + (long long)bm * K;
    const __half* Bg = B + (long long)bn * K;

    float acc[4][4][4];
    #pragma unroll
    for (int m = 0; m < 4; m++)
        #pragma unroll
        for (int n = 0; n < 4; n++)
            #pragma unroll
            for (int e = 0; e < 4; e++) acc[m][n][e] = 0.0f;

    gemm_mainloop<0>(Ag, Bg, K, K, sbase, tid, acc);

    const int warpM = (wid >> 2) * 64, warpN = (wid & 3) * 32;
    const int r = lane >> 2, q = lane & 3;
    const int sel = bn >> 10;                   // 0=Q 1=K 2=V
    const float* bias = (sel == 0) ? bq : (sel == 1) ? bk : bv;
    uint32_t* O = (uint32_t*)((sel == 0) ? Q : (sel == 1) ? Kd : V);

    #pragma unroll
    for (int nt = 0; nt < 4; nt++) {
        int col = bn + warpN + nt * 8 + q * 2;   // even
        int cl  = col & 1023;
        float b0 = bias[cl], b1 = bias[cl + 1];
        float invf = (sel < 2) ? powf(10000.0f, -(float)cl * (1.0f / (float)D_DIM)) : 0.0f;
        #pragma unroll
        for (int mt = 0; mt < 4; mt++) {
            #pragma unroll
            for (int rr = 0; rr < 2; rr++) {
                int row = bm + warpM + mt * 16 + r + rr * 8;
                float v0 = acc[mt][nt][rr * 2 + 0] + b0;
                float v1 = acc[mt][nt][rr * 2 + 1] + b1;
                if (sel < 2) {
                    int s = row & (S_LEN - 1);
                    float sn, cs;
                    sincosf((float)s * invf, &sn, &cs);
                    float t0 = v0 * cs - v1 * sn;
                    float t1 = v0 * sn + v1 * cs;
                    v0 = t0; v1 = t1;
                }
                O[(long long)row * (D_DIM / 2) + (cl >> 1)] = pack_h2(v0, v1);
            }
        }
    }
}

// ---------------- merged fp32 -> fp16 conversion (x + 3 weights, one launch) ----------------
#define XN8 (M_ROWS * D_DIM / 8)          // 1048576 uint4-groups for x
#define WN8 (D_DIM * D_DIM / 8)           // 131072 per weight
__global__ void __launch_bounds__(256) cvt_all_kernel(
    const float* __restrict__ x, const float* __restrict__ wq,
    const float* __restrict__ wk, const float* __restrict__ wv,
    __half* __restrict__ X, __half* __restrict__ W)
{
    int i = blockIdx.x * 256 + threadIdx.x;
    const float* src;
    __half* dst;
    int off;
    if (i < XN8)                { src = x;  dst = X; off = i; }
    else if (i < XN8 + WN8)     { src = wq; dst = W;                    off = i - XN8; }
    else if (i < XN8 + 2 * WN8) { src = wk; dst = W + (size_t)8 * WN8;  off = i - XN8 - WN8; }
    else if (i < XN8 + 3 * WN8) { src = wv; dst = W + (size_t)16 * WN8; off = i - XN8 - 2 * WN8; }
    else return;

    const float4* in4 = (const float4*)src;
    float4 v0 = in4[2 * off], v1 = in4[2 * off + 1];
    uint4 o;
    o.x = pack_h2(v0.x, v0.y);
    o.y = pack_h2(v0.z, v0.w);
    o.z = pack_h2(v1.x, v1.y);
    o.w = pack_h2(v1.z, v1.w);
    ((uint4*)dst)[off] = o;
}

// ---------------- row softmax over S_LEN, fp32 in -> fp16 out ----------------
__global__ void __launch_bounds__(256) softmax_kernel(
    const float* __restrict__ P, __half* __restrict__ P16)
{
    const float* row = P + (long long)blockIdx.x * S_LEN;
    __half* ro = P16 + (long long)blockIdx.x * S_LEN;
    const int tid = threadIdx.x;
    __shared__ float red[8];

    float v[8];
    float m = -1e30f;
    #pragma unroll
    for (int i = 0; i < 8; i++) {
        v[i] = row[tid + i * 256];
        m = fmaxf(m, v[i]);
    }
    #pragma unroll
    for (int o = 16; o > 0; o >>= 1) m = fmaxf(m, __shfl_xor_sync(0xFFFFFFFFu, m, o));
    if ((tid & 31) == 0) red[tid >> 5] = m;
    __syncthreads();
    m = red[0];
    #pragma unroll
    for (int i = 1; i < 8; i++) m = fmaxf(m, red[i]);
    __syncthreads();

    float sum = 0.0f;
    #pragma unroll
    for (int i = 0; i < 8; i++) {
        v[i] = expf(v[i] - m);
        sum += v[i];
    }
    #pragma unroll
    for (int o = 16; o > 0; o >>= 1) sum += __shfl_xor_sync(0xFFFFFFFFu, sum, o);
    if ((tid & 31) == 0) red[tid >> 5] = sum;
    __syncthreads();
    sum = 0.0f;
    #pragma unroll
    for (int i = 0; i < 8; i++) sum += red[i];

    float inv = 1.0f / sum;
    #pragma unroll
    for (int i = 0; i < 8; i++) ro[tid + i * 256] = __float2half(v[i] * inv);
}

// ---------------- launch ----------------
extern "C" void kernel_launch(void* const* d_in, const int* in_sizes, int n_in,
                              void* d_out, int out_size)
{
    const float* x  = (const float*)d_in[0];
    const float* wq = (const float*)d_in[1];
    const float* bq = (const float*)d_in[2];
    const float* wk = (const float*)d_in[3];
    const float* bk = (const float*)d_in[4];
    const float* wv = (const float*)d_in[5];
    const float* bv = (const float*)d_in[6];
    float* out = (float*)d_out;

    __half *X, *W, *Q, *K, *V, *P16;
    float *Sc;
    cudaGetSymbolAddress((void**)&X,   g_X16);
    cudaGetSymbolAddress((void**)&W,   g_W16);
    cudaGetSymbolAddress((void**)&Q,   g_Q16);
    cudaGetSymbolAddress((void**)&K,   g_K16);
    cudaGetSymbolAddress((void**)&V,   g_V16);
    cudaGetSymbolAddress((void**)&Sc,  g_S);
    cudaGetSymbolAddress((void**)&P16, g_P16);

    cudaFuncSetAttribute(gemm_plain<0>, cudaFuncAttributeMaxDynamicSharedMemorySize, SMEM_GEMM_BYTES);
    cudaFuncSetAttribute(gemm_plain<1>, cudaFuncAttributeMaxDynamicSharedMemorySize, SMEM_GEMM_BYTES);
    cudaFuncSetAttribute(gemm_proj,     cudaFuncAttributeMaxDynamicSharedMemorySize, SMEM_GEMM_BYTES);

    // 0) merged fp32 -> fp16 conversions (x + wq|wk|wv), one launch
    {
        int total = XN8 + 3 * WN8;
        cvt_all_kernel<<<(total + 255) / 256, 256>>>(x, wq, wk, wv, X, W);
    }

    // 1) fused QKV projection + bias + RoPE (M=8192, N=3072, K=1024)
    dim3 gP(3 * D_DIM / 128, M_ROWS / 128, 1);
    gemm_proj<<<gP, 256, SMEM_GEMM_BYTES>>>(X, W, bq, bk, bv, Q, K, V);

    // 2) scores = Q @ K^T / 32, batched (M=2048, N=2048, K=1024)
    dim3 gS(S_LEN / 128, S_LEN / 128, B_SZ);
    gemm_plain<0><<<gS, 256, SMEM_GEMM_BYTES>>>(Q, K, Sc, S_LEN, D_DIM,
                                                (long long)S_LEN * D_DIM, (long long)S_LEN * D_DIM,
                                                (long long)S_LEN * S_LEN, 0.03125f);

    // 3) softmax -> fp16
    softmax_kernel<<<M_ROWS, 256>>>(Sc, P16);

    // 4) out = P @ V (V row-major [s][d], NN via ldmatrix.trans), batched
    dim3 gO(D_DIM / 128, S_LEN / 128, B_SZ);
    gemm_plain<1><<<gO, 256, SMEM_GEMM_BYTES>>>(P16, V, out, D_DIM, S_LEN,
                                                (long long)S_LEN * S_LEN, (long long)S_LEN * D_DIM,
                                                (long long)S_LEN * D_DIM, 1.0f);
}